// round 1
// baseline (speedup 1.0000x reference)
#include <cuda_runtime.h>
#include <cuda_bf16.h>

// BoxFilter r=8 (k=17), separable, zero padding, fused H+V passes in one kernel.
// Input  x: [8, 32, 512, 512] f32 -> 256 images of 512x512.
// Output same shape.

#define RAD 8
#define KW  (2 * RAD + 1)          // 17
#define TILE_W 64
#define TILE_H 64
#define IN_W  (TILE_W + 2 * RAD)   // 80
#define IN_H  (TILE_H + 2 * RAD)   // 80
#define IN_PITCH (IN_W + 1)        // 81 (odd -> conflict-free cross-row access)
#define HS_PITCH (TILE_W + 1)      // 65 (odd -> conflict-free cross-row access)
#define NTHREADS 256

__global__ __launch_bounds__(NTHREADS)
void box_filter_fused(const float* __restrict__ in, float* __restrict__ out,
                      int H, int W) {
    __shared__ float s_in[IN_H * IN_PITCH];  // 80*81*4 = 25,920 B
    __shared__ float s_h [IN_H * HS_PITCH]; // 80*65*4 = 20,800 B  (total 46.7 KB)

    const int img = blockIdx.z;
    const int x0  = blockIdx.x * TILE_W;
    const int y0  = blockIdx.y * TILE_H;
    const int tid = threadIdx.x;

    const float* __restrict__ src = in + (size_t)img * H * W;

    // ---- Phase A: load 80x80 input tile with zero padding (coalesced) ----
    #pragma unroll 4
    for (int i = tid; i < IN_H * IN_W; i += NTHREADS) {
        int r = i / IN_W;
        int c = i - r * IN_W;
        int gy = y0 - RAD + r;
        int gx = x0 - RAD + c;
        float v = 0.0f;
        if (gy >= 0 && gy < H && gx >= 0 && gx < W)
            v = src[(size_t)gy * W + gx];
        s_in[r * IN_PITCH + c] = v;
    }
    __syncthreads();

    // ---- Phase B: horizontal running-window sums ----
    // hsum[row][c] = sum of s_in[row][c .. c+16], for all 80 rows, 64 cols.
    // 320 tasks: (row, 16-col strip).
    for (int t = tid; t < IN_H * 4; t += NTHREADS) {
        int row = t % IN_H;          // warp lanes -> distinct rows (pitch odd: no conflicts)
        int cb  = t / IN_H;          // 0..3
        int c0  = cb * 16;
        const float* rp = &s_in[row * IN_PITCH];
        float* hp = &s_h[row * HS_PITCH];

        float sum = 0.0f;
        #pragma unroll
        for (int j = 0; j < KW; j++) sum += rp[c0 + j];
        hp[c0] = sum;

        #pragma unroll
        for (int c = 1; c < 16; c++) {
            sum += rp[c0 + c + KW - 1] - rp[c0 + c - 1];
            hp[c0 + c] = sum;
        }
    }
    __syncthreads();

    // ---- Phase C: vertical running-window sums + write ----
    // out tile-local row y uses hsum rows y .. y+16.
    // 256 tasks: (col, 16-row strip). Warp lanes = consecutive cols -> coalesced stores.
    {
        const float scale = 1.0f / ((float)KW * (float)KW);
        int col = tid % TILE_W;
        int rb  = tid / TILE_W;      // 0..3
        int r0  = rb * 16;

        float* __restrict__ dst = out + (size_t)img * H * W;
        int gx = x0 + col;

        float sum = 0.0f;
        #pragma unroll
        for (int j = 0; j < KW; j++) sum += s_h[(r0 + j) * HS_PITCH + col];
        dst[(size_t)(y0 + r0) * W + gx] = sum * scale;

        #pragma unroll
        for (int i = 1; i < 16; i++) {
            sum += s_h[(r0 + i + KW - 1) * HS_PITCH + col]
                 - s_h[(r0 + i - 1)      * HS_PITCH + col];
            dst[(size_t)(y0 + r0 + i) * W + gx] = sum * scale;
        }
    }
}

extern "C" void kernel_launch(void* const* d_in, const int* in_sizes, int n_in,
                              void* d_out, int out_size) {
    const float* x = (const float*)d_in[0];
    float* out = (float*)d_out;

    const int N = 8, C = 32, H = 512, W = 512;
    (void)in_sizes; (void)n_in; (void)out_size;

    dim3 grid(W / TILE_W, H / TILE_H, N * C);  // 8 x 8 x 256 = 16384 blocks
    box_filter_fused<<<grid, NTHREADS>>>(x, out, H, W);
}

// round 2
// speedup vs baseline: 1.3820x; 1.3820x over previous
#include <cuda_runtime.h>
#include <cuda_bf16.h>

// BoxFilter r=8 (k=17), separable, zero padding.
// Fused: global->registers horizontal running sums -> smem -> vertical running
// sums -> global. No input staging tile (saves smem + the Phase-A ALU storm).
// Input x: [8, 32, 512, 512] f32 (256 images of 512x512), same-shape output.

#define RAD 8
#define KW  (2 * RAD + 1)          // 17
#define TILE_W 64
#define TILE_H 64
#define HS_ROWS (TILE_H + 2 * RAD) // 80 h-sum rows needed
#define HS_PITCH (TILE_W + 1)      // 65 (odd -> conflict-free cross-row smem)
#define NTHREADS 256

__global__ __launch_bounds__(NTHREADS)
void box_filter_fused(const float* __restrict__ in, float* __restrict__ out,
                      int H, int W) {
    __shared__ float s_h[HS_ROWS * HS_PITCH];  // 80*65*4 = 20,800 B

    const int img = blockIdx.z;
    const int x0  = blockIdx.x * TILE_W;
    const int y0  = blockIdx.y * TILE_H;
    const int tid = threadIdx.x;

    const float* __restrict__ src = in + (size_t)img * H * W;

    // ---- Phase B (fused with load): horizontal running-window sums ----
    // 320 tasks: (row 0..79, 16-col strip 0..3). Each task loads 32 consecutive
    // input floats (8 x float4, each vec4 fully in- or out-of-range because
    // RAD and strip offsets are multiples of 4) and emits 16 h-sums.
    #pragma unroll
    for (int t = tid; t < HS_ROWS * 4; t += NTHREADS) {
        const int row = t >> 2;            // 0..79
        const int c0  = (t & 3) << 4;      // 0,16,32,48
        const int gy  = y0 - RAD + row;
        const bool yok = (unsigned)gy < (unsigned)H;

        float v[32];
        const int gxb0 = x0 - RAD + c0;    // multiple of 4
        const float* rowp = src + (size_t)(yok ? gy : 0) * W;

        #pragma unroll
        for (int j = 0; j < 8; j++) {
            const int gxb = gxb0 + 4 * j;
            float4 q = make_float4(0.f, 0.f, 0.f, 0.f);
            if (yok && (unsigned)gxb <= (unsigned)(W - 4))
                q = *reinterpret_cast<const float4*>(rowp + gxb);
            v[4*j + 0] = q.x; v[4*j + 1] = q.y;
            v[4*j + 2] = q.z; v[4*j + 3] = q.w;
        }

        float* hp = &s_h[row * HS_PITCH + c0];
        float sum = 0.0f;
        #pragma unroll
        for (int j = 0; j < KW; j++) sum += v[j];
        hp[0] = sum;
        #pragma unroll
        for (int c = 1; c < 16; c++) {
            sum += v[c + KW - 1] - v[c - 1];
            hp[c] = sum;
        }
    }
    __syncthreads();

    // ---- Phase C: vertical running-window sums + coalesced store ----
    // 256 tasks: (col 0..63, 16-row strip 0..3). Lanes = consecutive cols.
    {
        const float scale = 1.0f / ((float)KW * (float)KW);
        const int col = tid & (TILE_W - 1);
        const int r0  = (tid >> 6) << 4;   // 0,16,32,48

        float* __restrict__ dst = out + (size_t)img * H * W;
        const int gx = x0 + col;

        float sum = 0.0f;
        #pragma unroll
        for (int j = 0; j < KW; j++) sum += s_h[(r0 + j) * HS_PITCH + col];
        dst[(size_t)(y0 + r0) * W + gx] = sum * scale;

        #pragma unroll
        for (int i = 1; i < 16; i++) {
            sum += s_h[(r0 + i + KW - 1) * HS_PITCH + col]
                 - s_h[(r0 + i - 1)      * HS_PITCH + col];
            dst[(size_t)(y0 + r0 + i) * W + gx] = sum * scale;
        }
    }
}

extern "C" void kernel_launch(void* const* d_in, const int* in_sizes, int n_in,
                              void* d_out, int out_size) {
    const float* x = (const float*)d_in[0];
    float* out = (float*)d_out;

    const int N = 8, C = 32, H = 512, W = 512;
    (void)in_sizes; (void)n_in; (void)out_size;

    dim3 grid(W / TILE_W, H / TILE_H, N * C);  // 8 x 8 x 256 = 16384 blocks
    box_filter_fused<<<grid, NTHREADS>>>(x, out, H, W);
}

// round 3
// speedup vs baseline: 1.3924x; 1.0076x over previous
#include <cuda_runtime.h>
#include <cuda_bf16.h>

// BoxFilter r=8 (k=17), separable, zero padding, fused in one kernel.
// Staged: coalesced float4 global->smem tile, LDS.128-fed horizontal running
// sums -> smem (STS.128), vertical running sums -> coalesced global store.
// Input x: [8, 32, 512, 512] f32 (256 images of 512x512), same-shape output.

#define RAD 8
#define KW  (2 * RAD + 1)          // 17
#define TILE_W 64
#define TILE_H 64
#define IN_W  (TILE_W + 2 * RAD)   // 80
#define IN_H  (TILE_H + 2 * RAD)   // 80
#define IN_PITCH 84                // floats; 84*4=336B (16B-mult); 21 mod 8 = 5 -> LDS.128 conflict-free across rows
#define HS_PITCH 68                // floats; 68*4=272B (16B-mult); Phase-C col reads conflict-free (lanes=cols)
#define NTHREADS 256

__global__ __launch_bounds__(NTHREADS)
void box_filter_fused(const float* __restrict__ in, float* __restrict__ out,
                      int H, int W) {
    __shared__ float s_in[IN_H * IN_PITCH];   // 80*84*4 = 26,880 B
    __shared__ float s_h [IN_H * HS_PITCH];   // 80*68*4 = 21,760 B  (total 48,640 B)

    const int img = blockIdx.z;
    const int x0  = blockIdx.x * TILE_W;
    const int y0  = blockIdx.y * TILE_H;
    const int tid = threadIdx.x;

    const float* __restrict__ src = in + (size_t)img * H * W;

    // ---- Phase A: coalesced vectorized tile load (80 rows x 20 float4) ----
    // Zero padding: since x0-RAD is 4-aligned, every float4 is fully in- or
    // fully out-of-range -> one unsigned compare per vector.
    #pragma unroll 4
    for (int i = tid; i < IN_H * 20; i += NTHREADS) {
        const int r  = i / 20;
        const int q  = i - r * 20;
        const int gy = y0 - RAD + r;
        const int gx = x0 - RAD + 4 * q;
        float4 v = make_float4(0.f, 0.f, 0.f, 0.f);
        if ((unsigned)gy < (unsigned)H && (unsigned)gx <= (unsigned)(W - 4))
            v = *reinterpret_cast<const float4*>(src + (size_t)gy * W + gx);
        *reinterpret_cast<float4*>(&s_in[r * IN_PITCH + 4 * q]) = v;
    }
    __syncthreads();

    // ---- Phase B: horizontal running-window sums (smem -> regs -> smem) ----
    // 320 tasks: (row 0..79, 16-col strip 0..3). Lane -> consecutive rows so
    // LDS.128 across the warp hits distinct bank groups.
    for (int t = tid; t < IN_H * 4; t += NTHREADS) {
        const int row = t % IN_H;          // consecutive lanes -> consecutive rows
        const int c0  = (t / IN_H) << 4;   // 0,16,32,48

        const float* p = &s_in[row * IN_PITCH + c0];
        float v[32];
        #pragma unroll
        for (int j = 0; j < 8; j++) {
            float4 q = *reinterpret_cast<const float4*>(p + 4 * j);
            v[4*j + 0] = q.x; v[4*j + 1] = q.y;
            v[4*j + 2] = q.z; v[4*j + 3] = q.w;
        }

        float h[16];
        float sum = 0.0f;
        #pragma unroll
        for (int j = 0; j < KW; j++) sum += v[j];
        h[0] = sum;
        #pragma unroll
        for (int c = 1; c < 16; c++) {
            sum += v[c + KW - 1] - v[c - 1];
            h[c] = sum;
        }

        float4* hp = reinterpret_cast<float4*>(&s_h[row * HS_PITCH + c0]);
        #pragma unroll
        for (int j = 0; j < 4; j++)
            hp[j] = make_float4(h[4*j], h[4*j+1], h[4*j+2], h[4*j+3]);
    }
    __syncthreads();

    // ---- Phase C: vertical running-window sums + coalesced store ----
    // 256 tasks: (col 0..63, 16-row strip 0..3). Lanes = consecutive cols ->
    // conflict-free LDS, coalesced STG.
    {
        const float scale = 1.0f / ((float)KW * (float)KW);
        const int col = tid & (TILE_W - 1);
        const int r0  = (tid >> 6) << 4;   // 0,16,32,48

        float* __restrict__ dst = out + (size_t)img * H * W;
        const int gx = x0 + col;

        float sum = 0.0f;
        #pragma unroll
        for (int j = 0; j < KW; j++) sum += s_h[(r0 + j) * HS_PITCH + col];
        dst[(size_t)(y0 + r0) * W + gx] = sum * scale;

        #pragma unroll
        for (int i = 1; i < 16; i++) {
            sum += s_h[(r0 + i + KW - 1) * HS_PITCH + col]
                 - s_h[(r0 + i - 1)      * HS_PITCH + col];
            dst[(size_t)(y0 + r0 + i) * W + gx] = sum * scale;
        }
    }
}

extern "C" void kernel_launch(void* const* d_in, const int* in_sizes, int n_in,
                              void* d_out, int out_size) {
    const float* x = (const float*)d_in[0];
    float* out = (float*)d_out;

    const int N = 8, C = 32, H = 512, W = 512;
    (void)in_sizes; (void)n_in; (void)out_size;

    dim3 grid(W / TILE_W, H / TILE_H, N * C);  // 8 x 8 x 256 = 16384 blocks
    box_filter_fused<<<grid, NTHREADS>>>(x, out, H, W);
}

// round 4
// speedup vs baseline: 1.8616x; 1.3370x over previous
#include <cuda_runtime.h>
#include <cuda_bf16.h>

// BoxFilter r=8 (k=17), separable, zero padding, fused in one kernel.
// Phase A: cp.async (LDGSTS.128 + zfill) tile load, no register round-trip.
// Phase B: LDS.128-fed horizontal running sums -> smem (STS.128).
// Phase C: 32 register-resident column values -> vertical running sums -> STG.
// Input x: [8, 32, 512, 512] f32 (256 images of 512x512), same-shape output.

#define RAD 8
#define KW  (2 * RAD + 1)          // 17
#define TILE_W 64
#define TILE_H 64
#define IN_W  (TILE_W + 2 * RAD)   // 80
#define IN_H  (TILE_H + 2 * RAD)   // 80
#define IN_PITCH 84                // 21 vec4/row, 21 mod 8 = 5 -> LDS.128 conflict-free across rows
#define HS_PITCH 68                // 16B-mult; Phase-C col reads conflict-free (lanes=cols)
#define NTHREADS 256

__global__ __launch_bounds__(NTHREADS)
void box_filter_fused(const float* __restrict__ in, float* __restrict__ out,
                      int H, int W) {
    __shared__ float s_in[IN_H * IN_PITCH];   // 80*84*4 = 26,880 B
    __shared__ float s_h [IN_H * HS_PITCH];   // 80*68*4 = 21,760 B

    const int img = blockIdx.z;
    const int x0  = blockIdx.x * TILE_W;
    const int y0  = blockIdx.y * TILE_H;
    const int tid = threadIdx.x;

    const float* __restrict__ src = in + (size_t)img * H * W;

    // ---- Phase A: cp.async tile load (80 rows x 20 float4), zero-filled OOB ----
    // x0-RAD is 4-float aligned, so each float4 is fully in- or out-of-range.
    #pragma unroll 4
    for (int i = tid; i < IN_H * 20; i += NTHREADS) {
        const int r  = i / 20;
        const int q  = i - r * 20;
        const int gy = y0 - RAD + r;
        const int gx = x0 - RAD + 4 * q;
        const bool ok = ((unsigned)gy < (unsigned)H) &&
                        ((unsigned)gx <= (unsigned)(W - 4));
        const float* gptr = src + (ok ? ((size_t)gy * W + gx) : 0);
        unsigned saddr = (unsigned)__cvta_generic_to_shared(&s_in[r * IN_PITCH + 4 * q]);
        const int sz = ok ? 16 : 0;  // src-size 0 -> zero fill
        asm volatile("cp.async.cg.shared.global [%0], [%1], 16, %2;\n"
                     :: "r"(saddr), "l"(gptr), "r"(sz));
    }
    asm volatile("cp.async.commit_group;\n" ::: "memory");
    asm volatile("cp.async.wait_group 0;\n" ::: "memory");
    __syncthreads();

    // ---- Phase B: horizontal running-window sums (smem -> regs -> smem) ----
    // 320 tasks: (row 0..79, 16-col strip 0..3). Lane -> consecutive rows.
    for (int t = tid; t < IN_H * 4; t += NTHREADS) {
        const int row = t % IN_H;
        const int c0  = (t / IN_H) << 4;   // 0,16,32,48

        const float* p = &s_in[row * IN_PITCH + c0];
        float v[32];
        #pragma unroll
        for (int j = 0; j < 8; j++) {
            float4 q = *reinterpret_cast<const float4*>(p + 4 * j);
            v[4*j + 0] = q.x; v[4*j + 1] = q.y;
            v[4*j + 2] = q.z; v[4*j + 3] = q.w;
        }

        float h[16];
        float sum = 0.0f;
        #pragma unroll
        for (int j = 0; j < KW; j++) sum += v[j];
        h[0] = sum;
        #pragma unroll
        for (int c = 1; c < 16; c++) {
            sum += v[c + KW - 1] - v[c - 1];
            h[c] = sum;
        }

        float4* hp = reinterpret_cast<float4*>(&s_h[row * HS_PITCH + c0]);
        #pragma unroll
        for (int j = 0; j < 4; j++)
            hp[j] = make_float4(h[4*j], h[4*j+1], h[4*j+2], h[4*j+3]);
    }
    __syncthreads();

    // ---- Phase C: vertical running sums from registers + coalesced store ----
    // 256 tasks: (col 0..63, 16-row strip 0..3). Each task needs exactly the
    // 32 h-sums rows r0..r0+31 at its column: load once into registers.
    {
        const float scale = 1.0f / ((float)KW * (float)KW);
        const int col = tid & (TILE_W - 1);
        const int r0  = (tid >> 6) << 4;   // 0,16,32,48

        float v[32];
        #pragma unroll
        for (int j = 0; j < 32; j++)
            v[j] = s_h[(r0 + j) * HS_PITCH + col];

        float* __restrict__ dst = out + (size_t)img * H * W;
        const int gx = x0 + col;

        float sum = 0.0f;
        #pragma unroll
        for (int j = 0; j < KW; j++) sum += v[j];
        dst[(size_t)(y0 + r0) * W + gx] = sum * scale;

        #pragma unroll
        for (int i = 1; i < 16; i++) {
            sum += v[i + KW - 1] - v[i - 1];
            dst[(size_t)(y0 + r0 + i) * W + gx] = sum * scale;
        }
    }
}

extern "C" void kernel_launch(void* const* d_in, const int* in_sizes, int n_in,
                              void* d_out, int out_size) {
    const float* x = (const float*)d_in[0];
    float* out = (float*)d_out;

    const int N = 8, C = 32, H = 512, W = 512;
    (void)in_sizes; (void)n_in; (void)out_size;

    dim3 grid(W / TILE_W, H / TILE_H, N * C);  // 8 x 8 x 256 = 16384 blocks
    box_filter_fused<<<grid, NTHREADS>>>(x, out, H, W);
}

// round 5
// speedup vs baseline: 2.0213x; 1.0857x over previous
#include <cuda_runtime.h>
#include <cuda_bf16.h>

// BoxFilter r=8 (k=17), separable, zero padding, fused in one kernel.
// Phase A: cp.async (zfill) 80x80 tile load.
// Then two 32-column halves, each: Phase B horizontal running sums into a
// small s_h (11.5 KB), Phase C vertical running sums from registers -> STG.
// Smem 38.4 KB -> 5 CTAs/SM (was 4).
// Input x: [8, 32, 512, 512] f32 (256 images of 512x512), same-shape output.

#define RAD 8
#define KW  (2 * RAD + 1)          // 17
#define TILE_W 64
#define TILE_H 64
#define IN_W  (TILE_W + 2 * RAD)   // 80
#define IN_H  (TILE_H + 2 * RAD)   // 80
#define IN_PITCH 84                // 21x16B rows, odd 16B stride -> conflict-free
#define HALF_W 32
#define HS_PITCH 36                // 9x16B rows, odd 16B stride -> conflict-free
#define NTHREADS 256

__global__ __launch_bounds__(NTHREADS)
void box_filter_fused(const float* __restrict__ in, float* __restrict__ out,
                      int H, int W) {
    __shared__ float s_in[IN_H * IN_PITCH];   // 80*84*4 = 26,880 B
    __shared__ float s_h [IN_H * HS_PITCH];   // 80*36*4 = 11,520 B (total 38.4 KB)

    const int img = blockIdx.z;
    const int x0  = blockIdx.x * TILE_W;
    const int y0  = blockIdx.y * TILE_H;
    const int tid = threadIdx.x;

    const float* __restrict__ src = in + (size_t)img * H * W;
    float* __restrict__ dst = out + (size_t)img * H * W;

    // ---- Phase A: cp.async tile load (80 rows x 20 float4), zero-filled OOB ----
    #pragma unroll 4
    for (int i = tid; i < IN_H * 20; i += NTHREADS) {
        const int r  = i / 20;
        const int q  = i - r * 20;
        const int gy = y0 - RAD + r;
        const int gx = x0 - RAD + 4 * q;
        const bool ok = ((unsigned)gy < (unsigned)H) &&
                        ((unsigned)gx <= (unsigned)(W - 4));
        const float* gptr = src + (ok ? ((size_t)gy * W + gx) : 0);
        unsigned saddr = (unsigned)__cvta_generic_to_shared(&s_in[r * IN_PITCH + 4 * q]);
        const int sz = ok ? 16 : 0;  // src-size 0 -> zero fill
        asm volatile("cp.async.cg.shared.global [%0], [%1], 16, %2;\n"
                     :: "r"(saddr), "l"(gptr), "r"(sz));
    }
    asm volatile("cp.async.commit_group;\n" ::: "memory");
    asm volatile("cp.async.wait_group 0;\n" ::: "memory");
    __syncthreads();

    const float scale = 1.0f / ((float)KW * (float)KW);

    #pragma unroll
    for (int half = 0; half < 2; half++) {
        const int c_base = half * HALF_W;   // 0 or 32 (tile-local output col base)

        // ---- Phase B: horizontal running sums for this half ----
        // 160 tasks: (row 0..79, 16-col strip 0..1). Output col c (local) uses
        // inputs (c_base + strip*16) .. +31 in s_in coords (offset by 0: s_in
        // col c corresponds to global x0-RAD+c; output local col c uses s_in
        // cols c..c+16; strip covers outputs c_base+strip*16 .. +15 -> inputs
        // c_base+strip*16 .. c_base+strip*16+31).
        if (tid < IN_H * 2) {
            const int row = tid % IN_H;          // consecutive lanes -> rows
            const int stp = tid / IN_H;          // 0..1
            const int ci  = c_base + stp * 16;   // input col start in s_in

            const float* p = &s_in[row * IN_PITCH + ci];
            float v[32];
            #pragma unroll
            for (int j = 0; j < 8; j++) {
                float4 q = *reinterpret_cast<const float4*>(p + 4 * j);
                v[4*j + 0] = q.x; v[4*j + 1] = q.y;
                v[4*j + 2] = q.z; v[4*j + 3] = q.w;
            }

            float h[16];
            float sum = 0.0f;
            #pragma unroll
            for (int j = 0; j < KW; j++) sum += v[j];
            h[0] = sum;
            #pragma unroll
            for (int c = 1; c < 16; c++) {
                sum += v[c + KW - 1] - v[c - 1];
                h[c] = sum;
            }

            float4* hp = reinterpret_cast<float4*>(&s_h[row * HS_PITCH + stp * 16]);
            #pragma unroll
            for (int j = 0; j < 4; j++)
                hp[j] = make_float4(h[4*j], h[4*j+1], h[4*j+2], h[4*j+3]);
        }
        __syncthreads();

        // ---- Phase C: vertical running sums from registers + store ----
        // 128 tasks: (local col 0..31, 16-row seg 0..3). Lanes = consecutive
        // cols -> conflict-free LDS, coalesced STG.
        if (tid < HALF_W * 4) {
            const int col = tid & (HALF_W - 1);
            const int r0  = (tid >> 5) << 4;     // 0,16,32,48

            float v[32];
            #pragma unroll
            for (int j = 0; j < 32; j++)
                v[j] = s_h[(r0 + j) * HS_PITCH + col];

            const int gx = x0 + c_base + col;

            float sum = 0.0f;
            #pragma unroll
            for (int j = 0; j < KW; j++) sum += v[j];
            dst[(size_t)(y0 + r0) * W + gx] = sum * scale;

            #pragma unroll
            for (int i = 1; i < 16; i++) {
                sum += v[i + KW - 1] - v[i - 1];
                dst[(size_t)(y0 + r0 + i) * W + gx] = sum * scale;
            }
        }
        if (half == 0) __syncthreads();
    }
}

extern "C" void kernel_launch(void* const* d_in, const int* in_sizes, int n_in,
                              void* d_out, int out_size) {
    const float* x = (const float*)d_in[0];
    float* out = (float*)d_out;

    const int N = 8, C = 32, H = 512, W = 512;
    (void)in_sizes; (void)n_in; (void)out_size;

    dim3 grid(W / TILE_W, H / TILE_H, N * C);  // 8 x 8 x 256 = 16384 blocks
    box_filter_fused<<<grid, NTHREADS>>>(x, out, H, W);
}

// round 6
// speedup vs baseline: 2.1001x; 1.0390x over previous
#include <cuda_runtime.h>
#include <cuda_bf16.h>

// BoxFilter r=8 (k=17), separable, zero padding, fused in one kernel.
// Phase A: cp.async (zfill) 80x80 tile load.
// Two 32-column halves, each: Phase B horizontal running sums into a small
// s_h, Phase C vertical running sums from registers -> STG.
// __launch_bounds__(256, 6): cap regs at 40 so 6 CTAs/SM fit (reg file),
// smem 38.4 KB x 6 = 230.4 KB <= 228 KB HW aggregate (just fits).
// Input x: [8, 32, 512, 512] f32 (256 images of 512x512), same-shape output.

#define RAD 8
#define KW  (2 * RAD + 1)          // 17
#define TILE_W 64
#define TILE_H 64
#define IN_W  (TILE_W + 2 * RAD)   // 80
#define IN_H  (TILE_H + 2 * RAD)   // 80
#define IN_PITCH 84                // 21x16B rows, odd 16B stride -> conflict-free
#define HALF_W 32
#define HS_PITCH 36                // 9x16B rows, odd 16B stride -> conflict-free
#define NTHREADS 256

__global__ __launch_bounds__(NTHREADS, 6)
void box_filter_fused(const float* __restrict__ in, float* __restrict__ out,
                      int H, int W) {
    __shared__ float s_in[IN_H * IN_PITCH];   // 80*84*4 = 26,880 B
    __shared__ float s_h [IN_H * HS_PITCH];   // 80*36*4 = 11,520 B (total 38,400 B)

    const int img = blockIdx.z;
    const int x0  = blockIdx.x * TILE_W;
    const int y0  = blockIdx.y * TILE_H;
    const int tid = threadIdx.x;

    const float* __restrict__ src = in + (size_t)img * H * W;
    float* __restrict__ dst = out + (size_t)img * H * W;

    // ---- Phase A: cp.async tile load (80 rows x 20 float4), zero-filled OOB ----
    // 1600 vec4 items over 256 threads: hoist the /20, then step row/col
    // incrementally (256 = 12*20 + 16 -> dr=12, dq=16 per iteration).
    {
        int r = tid / 20;
        int q = tid - r * 20;
        #pragma unroll
        for (int it = 0; it < 7; it++) {
            const int idx = tid + it * NTHREADS;
            if (idx < IN_H * 20) {
                const int gy = y0 - RAD + r;
                const int gx = x0 - RAD + 4 * q;
                const bool ok = ((unsigned)gy < (unsigned)H) &&
                                ((unsigned)gx <= (unsigned)(W - 4));
                const float* gptr = src + (ok ? ((size_t)gy * W + gx) : 0);
                unsigned saddr = (unsigned)__cvta_generic_to_shared(&s_in[r * IN_PITCH + 4 * q]);
                const int sz = ok ? 16 : 0;  // src-size 0 -> zero fill
                asm volatile("cp.async.cg.shared.global [%0], [%1], 16, %2;\n"
                             :: "r"(saddr), "l"(gptr), "r"(sz));
            }
            r += 12; q += 16;
            if (q >= 20) { q -= 20; r += 1; }
        }
    }
    asm volatile("cp.async.commit_group;\n" ::: "memory");
    asm volatile("cp.async.wait_group 0;\n" ::: "memory");
    __syncthreads();

    const float scale = 1.0f / ((float)KW * (float)KW);

    #pragma unroll
    for (int half = 0; half < 2; half++) {
        const int c_base = half * HALF_W;   // tile-local output col base: 0 or 32

        // ---- Phase B: horizontal running sums for this half ----
        // 160 tasks: (row 0..79, 16-col strip 0..1). Lane -> consecutive rows.
        if (tid < IN_H * 2) {
            const int row = tid % IN_H;
            const int stp = tid / IN_H;          // 0..1
            const int ci  = c_base + stp * 16;   // input col start in s_in

            const float* p = &s_in[row * IN_PITCH + ci];
            float v[32];
            #pragma unroll
            for (int j = 0; j < 8; j++) {
                float4 q = *reinterpret_cast<const float4*>(p + 4 * j);
                v[4*j + 0] = q.x; v[4*j + 1] = q.y;
                v[4*j + 2] = q.z; v[4*j + 3] = q.w;
            }

            float h[16];
            float sum = 0.0f;
            #pragma unroll
            for (int j = 0; j < KW; j++) sum += v[j];
            h[0] = sum;
            #pragma unroll
            for (int c = 1; c < 16; c++) {
                sum += v[c + KW - 1] - v[c - 1];
                h[c] = sum;
            }

            float4* hp = reinterpret_cast<float4*>(&s_h[row * HS_PITCH + stp * 16]);
            #pragma unroll
            for (int j = 0; j < 4; j++)
                hp[j] = make_float4(h[4*j], h[4*j+1], h[4*j+2], h[4*j+3]);
        }
        __syncthreads();

        // ---- Phase C: vertical running sums from registers + store ----
        // 128 tasks: (local col 0..31, 16-row seg 0..3). Lanes = consecutive
        // cols -> conflict-free LDS, coalesced STG.
        if (tid < HALF_W * 4) {
            const int col = tid & (HALF_W - 1);
            const int r0  = (tid >> 5) << 4;     // 0,16,32,48

            float v[32];
            #pragma unroll
            for (int j = 0; j < 32; j++)
                v[j] = s_h[(r0 + j) * HS_PITCH + col];

            const int gx = x0 + c_base + col;

            float sum = 0.0f;
            #pragma unroll
            for (int j = 0; j < KW; j++) sum += v[j];
            dst[(size_t)(y0 + r0) * W + gx] = sum * scale;

            #pragma unroll
            for (int i = 1; i < 16; i++) {
                sum += v[i + KW - 1] - v[i - 1];
                dst[(size_t)(y0 + r0 + i) * W + gx] = sum * scale;
            }
        }
        if (half == 0) __syncthreads();
    }
}

extern "C" void kernel_launch(void* const* d_in, const int* in_sizes, int n_in,
                              void* d_out, int out_size) {
    const float* x = (const float*)d_in[0];
    float* out = (float*)d_out;

    const int N = 8, C = 32, H = 512, W = 512;
    (void)in_sizes; (void)n_in; (void)out_size;

    dim3 grid(W / TILE_W, H / TILE_H, N * C);  // 8 x 8 x 256 = 16384 blocks
    box_filter_fused<<<grid, NTHREADS>>>(x, out, H, W);
}